// round 12
// baseline (speedup 1.0000x reference)
#include <cuda_runtime.h>
#include <cuda_bf16.h>
#include <math.h>
#include <stdint.h>

#define ETHREADS 512
#define NTHREADS 256
#define M_TILE 256          // 16 warps x 16 rows
#define N_MAX 50000

#define STRIDE128 272
#define STRIDE64  144

// ---- padded bf16 weight images ----
#define IWCB 0        // Wcomb [128x128] s272 : 34816
#define IWE2 34816    // We2   [128x128] s272 : 34816
#define IWC  69632    // Wc    [128x64]  s144 : 18432
#define IMG_TOTAL 88064
__device__ __align__(16) unsigned char g_wimg[IMG_TOTAL];

// per-node m1 table: Y1 = relu(h@Wn1+b1)@Wn2, bf16 [N_MAX x 128]
__device__ __align__(16) __nv_bfloat16 g_Y1[(size_t)N_MAX * 128];

// ---- edge kernel smem (bytes) ----
#define WCB_OFF  0          // 34816
#define WE2_OFF  34816      // 34816
#define WC_OFF   69632      // 18432
#define SA_OFF   88064      // 256*272 = 69632   A = [t|eh]
#define SB2_OFF  157696     // 512
#define SSRC_OFF 158208     // 1024
#define SDST_OFF 159232     // 1024
#define ESMEM_BYTES 160256

// ---- node kernel smem ----
#define NW1_OFF 0
#define NW2_OFF (NW1_OFF + 64*STRIDE128)
#define NH_OFF  (NW2_OFF + 128*STRIDE128)
#define NX_OFF  (NH_OFF + 128*STRIDE64)
#define NB_OFF  (NX_OFF + 128*STRIDE128)
#define NSMEM_BYTES (NB_OFF + 512)

__device__ __forceinline__ uint32_t smem_u32(const void* p) {
    uint32_t a;
    asm("{ .reg .u64 t; cvta.to.shared.u64 t, %1; cvt.u32.u64 %0, t; }" : "=r"(a) : "l"(p));
    return a;
}
__device__ __forceinline__ uint32_t pack2_bf16(float a, float b) {
    __nv_bfloat162 p = __float22bfloat162_rn(make_float2(a, b));
    return *(unsigned int*)&p;
}
__device__ __forceinline__ uint2 pack4_bf16(float a, float b, float c, float d) {
    uint2 r; r.x = pack2_bf16(a, b); r.y = pack2_bf16(c, d); return r;
}
__device__ __forceinline__ float fast_tanh(float x) {
    float y;
    asm("tanh.approx.f32 %0, %1;" : "=f"(y) : "f"(x));
    return y;
}
__device__ __forceinline__ void ldsm_x4(uint32_t addr, uint32_t r[4]) {
    asm volatile("ldmatrix.sync.aligned.m8n8.x4.shared.b16 {%0,%1,%2,%3}, [%4];"
        : "=r"(r[0]), "=r"(r[1]), "=r"(r[2]), "=r"(r[3]) : "r"(addr));
}
__device__ __forceinline__ void ldsm_x4t(uint32_t addr, uint32_t r[4]) {
    asm volatile("ldmatrix.sync.aligned.m8n8.x4.trans.shared.b16 {%0,%1,%2,%3}, [%4];"
        : "=r"(r[0]), "=r"(r[1]), "=r"(r[2]), "=r"(r[3]) : "r"(addr));
}
__device__ __forceinline__ void mma16816(float d[4], const uint32_t a[4], const uint32_t b[2]) {
    asm volatile("mma.sync.aligned.m16n8k16.row.col.f32.bf16.bf16.f32 "
        "{%0,%1,%2,%3},{%4,%5,%6,%7},{%8,%9},{%0,%1,%2,%3};"
        : "+f"(d[0]), "+f"(d[1]), "+f"(d[2]), "+f"(d[3])
        : "r"(a[0]), "r"(a[1]), "r"(a[2]), "r"(a[3]), "r"(b[0]), "r"(b[1]));
}

// single-strip mma for node kernel
template<int KT, int NTH>
__device__ __forceinline__ void mma_stage(uint32_t aAddr, int aStride,
                                          uint32_t wAddr, int wStride,
                                          int m0, int n0, int lane,
                                          float acc[2][NTH][4]) {
#pragma unroll
    for (int mt = 0; mt < 2; ++mt)
#pragma unroll
        for (int n = 0; n < NTH; ++n)
#pragma unroll
            for (int e = 0; e < 4; ++e) acc[mt][n][e] = 0.f;
    const int krow = lane & 15;
    const int xoff = (lane >> 4) << 3;
#pragma unroll
    for (int k = 0; k < KT; ++k) {
        uint32_t a[2][4];
#pragma unroll
        for (int mt = 0; mt < 2; ++mt)
            ldsm_x4(aAddr + (uint32_t)(m0 + mt * 16 + krow) * aStride + (uint32_t)(k * 16 + xoff) * 2, a[mt]);
#pragma unroll
        for (int np = 0; np < NTH / 2; ++np) {
            uint32_t b[4];
            ldsm_x4t(wAddr + (uint32_t)(k * 16 + krow) * wStride + (uint32_t)(n0 + np * 16 + xoff) * 2, b);
            mma16816(acc[0][np * 2 + 0], a[0], b + 0);
            mma16816(acc[1][np * 2 + 0], a[1], b + 0);
            mma16816(acc[0][np * 2 + 1], a[0], b + 2);
            mma16816(acc[1][np * 2 + 1], a[1], b + 2);
        }
    }
}

__device__ __forceinline__ void load_weight_smem(char* smemc, int off, const float* __restrict__ W,
                                                 int K, int N, int stride, int tid, int nthr) {
    int n4 = (K * N) >> 2;
    for (int i = tid; i < n4; i += nthr) {
        int idx = i << 2;
        int r = idx / N, c = idx % N;
        float4 v = *(const float4*)(W + idx);
        *(uint2*)(smemc + off + r * stride + c * 2) = pack4_bf16(v.x, v.y, v.z, v.w);
    }
}

// build Wcomb = [[0.2*Wue@We1],[0.8*We1]] (fp32 accum) + We2 + Wc images
__global__ void convert_weights(const float* __restrict__ Wue, const float* __restrict__ We1,
                                const float* __restrict__ We2, const float* __restrict__ Wc) {
    int i = blockIdx.x * blockDim.x + threadIdx.x;
    if (i < 16384) {                // Wcomb 128x128 s272
        int r = i >> 7, c = i & 127;
        float v;
        if (r < 64) {
            float s = 0.f;
#pragma unroll 8
            for (int k = 0; k < 64; ++k) s += Wue[r * 64 + k] * We1[k * 128 + c];
            v = 0.2f * s;
        } else {
            v = 0.8f * We1[(r - 64) * 128 + c];
        }
        *(__nv_bfloat16*)(g_wimg + IWCB + r * STRIDE128 + c * 2) = __float2bfloat16(v);
    } else if (i < 32768) {         // We2 128x128 s272
        int j = i - 16384, r = j >> 7, c = j & 127;
        *(__nv_bfloat16*)(g_wimg + IWE2 + r * STRIDE128 + c * 2) = __float2bfloat16(We2[j]);
    } else if (i < 40960) {         // Wc 128x64 s144
        int j = i - 32768, r = j >> 6, c = j & 63;
        *(__nv_bfloat16*)(g_wimg + IWC + r * STRIDE64 + c * 2) = __float2bfloat16(Wc[j]);
    }
}

// =============== node kernel: Y1 table + out = h (residual init) ===============
__global__ __launch_bounds__(NTHREADS)
void node_kernel(const float* __restrict__ h,
                 const float* __restrict__ Wn1, const float* __restrict__ bn1,
                 const float* __restrict__ Wn2, float* __restrict__ out, int Nn)
{
    extern __shared__ char smem[];
    const uint32_t sbase = smem_u32(smem);
    const int tid = threadIdx.x;
    const int warp = tid >> 5;
    const int lane = tid & 31;
    const int mi = warp >> 1, nj = warp & 1;
    const int m0 = mi * 32, n0 = nj * 64;
    const int g = lane >> 2, q = lane & 3;
    const int r0 = blockIdx.x * 128;

    float* sB = (float*)(smem + NB_OFF);
    load_weight_smem(smem, NW1_OFF, Wn1, 64, 128, STRIDE128, tid, NTHREADS);
    load_weight_smem(smem, NW2_OFF, Wn2, 128, 128, STRIDE128, tid, NTHREADS);
    if (tid < 128) sB[tid] = bn1[tid];

    // load h rows -> bf16 smem; also out = h (residual init)
    for (int i = tid; i < 128 * 16; i += NTHREADS) {
        int r = i >> 4, d4 = i & 15;
        int nr = r0 + r;
        bool valid = (nr < Nn);
        if (!valid) nr = Nn - 1;
        float4 v = ((const float4*)(h + (size_t)nr * 64))[d4];
        if (valid) ((float4*)(out + (size_t)nr * 64))[d4] = v;
        *(uint2*)(smem + NH_OFF + r * STRIDE64 + d4 * 8) = pack4_bf16(v.x, v.y, v.z, v.w);
    }
    __syncthreads();

    float acc[2][8][4];
    mma_stage<4, 8>(sbase + NH_OFF, STRIDE64, sbase + NW1_OFF, STRIDE128, m0, n0, lane, acc);
#pragma unroll
    for (int mt = 0; mt < 2; ++mt)
#pragma unroll
        for (int n = 0; n < 8; ++n) {
            int col = n0 + n * 8 + q * 2;
            float b0 = sB[col], b1 = sB[col + 1];
            int rA = m0 + mt * 16 + g;
            *(uint32_t*)(smem + NX_OFF + rA * STRIDE128 + col * 2) =
                pack2_bf16(fmaxf(acc[mt][n][0] + b0, 0.f), fmaxf(acc[mt][n][1] + b1, 0.f));
            *(uint32_t*)(smem + NX_OFF + (rA + 8) * STRIDE128 + col * 2) =
                pack2_bf16(fmaxf(acc[mt][n][2] + b0, 0.f), fmaxf(acc[mt][n][3] + b1, 0.f));
        }
    __syncthreads();

    mma_stage<8, 8>(sbase + NX_OFF, STRIDE128, sbase + NW2_OFF, STRIDE128, m0, n0, lane, acc);
#pragma unroll
    for (int mt = 0; mt < 2; ++mt)
#pragma unroll
        for (int n = 0; n < 8; ++n) {
            int col = n0 + n * 8 + q * 2;
            int rA = m0 + mt * 16 + g;
            int nrA = r0 + rA, nrB = r0 + rA + 8;
            if (nrA < Nn)
                *(uint32_t*)(g_Y1 + (size_t)nrA * 128 + col) = pack2_bf16(acc[mt][n][0], acc[mt][n][1]);
            if (nrB < Nn)
                *(uint32_t*)(g_Y1 + (size_t)nrB * 128 + col) = pack2_bf16(acc[mt][n][2], acc[mt][n][3]);
        }
}

// =============== edge kernel: per-warp 16-row strip, register-chained stages ===============
__global__ __launch_bounds__(ETHREADS, 1)
void edge_kernel(const float* __restrict__ h, const float* __restrict__ eh,
                 const float* __restrict__ be1,
                 const int* __restrict__ src, const int* __restrict__ dst,
                 float* __restrict__ out, int E, int nTiles)
{
    extern __shared__ char smem[];
    const uint32_t sbase = smem_u32(smem);
    const int tid = threadIdx.x;
    const int warp = tid >> 5;
    const int lane = tid & 31;
    const int g = lane >> 2, q = lane & 3;
    const int krow = lane & 15;
    const int xoff = (lane >> 4) << 3;
    const int row0 = warp * 16;          // warp's 16-row strip

    float* sB2 = (float*)(smem + SB2_OFF);
    int* sSrc = (int*)(smem + SSRC_OFF);
    int* sDst = (int*)(smem + SDST_OFF);

    // ---- one-time: copy pre-built weight images into smem (resident) ----
    {
        const uint4* gsrc = (const uint4*)g_wimg;
        uint4* sdst = (uint4*)smem;   // WCB/WE2/WC are contiguous at offset 0
        for (int i = tid; i < IMG_TOTAL / 16; i += ETHREADS) sdst[i] = gsrc[i];
        if (tid < 128) sB2[tid] = be1[tid];
    }
    __syncthreads();

    const uint32_t wcb = sbase + WCB_OFF;
    const uint32_t we2 = sbase + WE2_OFF;
    const uint32_t wcc = sbase + WC_OFF;

    for (int tile = blockIdx.x; tile < nTiles; tile += gridDim.x) {
        const int e0 = tile * M_TILE;
        __syncthreads();   // [1] all warps finished prev tile (SA/idx free)

        if (tid < M_TILE) {
            long e = (long)e0 + tid;
            int eg = (e < E) ? (int)e : E - 1;
            sSrc[tid] = src[eg];
            sDst[tid] = dst[eg];
        }
        __syncthreads();   // [2] indices visible

        // gather: A = [ t = hs*hd (cols 0-63) | eh (cols 64-127) ]
        for (int i = tid; i < M_TILE * 16; i += ETHREADS) {
            int e = i >> 4, d4 = i & 15;
            int eg = e0 + e; if (eg >= E) eg = E - 1;
            float4 a = ((const float4*)(h + (size_t)sSrc[e] * 64))[d4];
            float4 b = ((const float4*)(h + (size_t)sDst[e] * 64))[d4];
            float4 ev = ((const float4*)(eh + (size_t)eg * 64))[d4];
            *(uint2*)(smem + SA_OFF + e * STRIDE128 + d4 * 8) =
                pack4_bf16(a.x * b.x, a.y * b.y, a.z * b.z, a.w * b.w);
            *(uint2*)(smem + SA_OFF + e * STRIDE128 + 128 + d4 * 8) =
                pack4_bf16(ev.x, ev.y, ev.z, ev.w);
        }
        __syncthreads();   // [3] A ready — from here each warp is independent

        // per-thread edge/node bookkeeping (rows row0+g and row0+g+8)
        const int rA = row0 + g, rB = row0 + g + 8;
        const int egA = e0 + rA, egB = e0 + rB;
        const int nodeA = sSrc[rA], nodeB = sSrc[rB];
        const int dA = sDst[rA], dB = sDst[rB];

        // ---- stage A: x2 = relu(A @ Wcomb + b2), acc -> A-fragments in regs ----
        uint32_t x2f[8][4];
        {
            uint32_t afrag[8][4];
            const uint32_t aBase = sbase + SA_OFF + (uint32_t)(row0 + krow) * STRIDE128;
#pragma unroll
            for (int k = 0; k < 8; ++k)
                ldsm_x4(aBase + (uint32_t)(k * 16 + xoff) * 2, afrag[k]);
#pragma unroll
            for (int c = 0; c < 8; ++c) {
                float acc[8];
#pragma unroll
                for (int e = 0; e < 8; ++e) acc[e] = 0.f;
#pragma unroll
                for (int k = 0; k < 8; ++k) {
                    uint32_t b[4];
                    ldsm_x4t(wcb + (uint32_t)(k * 16 + krow) * STRIDE128 + (uint32_t)(c * 16 + xoff) * 2, b);
                    mma16816(acc + 0, afrag[k], b + 0);
                    mma16816(acc + 4, afrag[k], b + 2);
                }
                int col = c * 16 + q * 2;
                float b0 = sB2[col], b1 = sB2[col + 1];
                float b2 = sB2[col + 8], b3 = sB2[col + 9];
                x2f[c][0] = pack2_bf16(fmaxf(acc[0] + b0, 0.f), fmaxf(acc[1] + b1, 0.f));
                x2f[c][1] = pack2_bf16(fmaxf(acc[2] + b0, 0.f), fmaxf(acc[3] + b1, 0.f));
                x2f[c][2] = pack2_bf16(fmaxf(acc[4] + b2, 0.f), fmaxf(acc[5] + b3, 0.f));
                x2f[c][3] = pack2_bf16(fmaxf(acc[6] + b2, 0.f), fmaxf(acc[7] + b3, 0.f));
            }
        }

        // ---- stage B: p = Y1[src] * (x2 @ We2), acc -> A-fragments in regs ----
        uint32_t pf[8][4];
        {
            const __nv_bfloat16* yA = g_Y1 + (size_t)nodeA * 128;
            const __nv_bfloat16* yB = g_Y1 + (size_t)nodeB * 128;
#pragma unroll
            for (int c = 0; c < 8; ++c) {
                float acc[8];
#pragma unroll
                for (int e = 0; e < 8; ++e) acc[e] = 0.f;
#pragma unroll
                for (int k = 0; k < 8; ++k) {
                    uint32_t b[4];
                    ldsm_x4t(we2 + (uint32_t)(k * 16 + krow) * STRIDE128 + (uint32_t)(c * 16 + xoff) * 2, b);
                    mma16816(acc + 0, x2f[k], b + 0);
                    mma16816(acc + 4, x2f[k], b + 2);
                }
                int col = c * 16 + q * 2;
                uint32_t ya0 = *(const uint32_t*)(yA + col);
                uint32_t yb0 = *(const uint32_t*)(yB + col);
                uint32_t ya1 = *(const uint32_t*)(yA + col + 8);
                uint32_t yb1 = *(const uint32_t*)(yB + col + 8);
                __nv_bfloat162 hA0 = *(__nv_bfloat162*)&ya0;
                __nv_bfloat162 hB0 = *(__nv_bfloat162*)&yb0;
                __nv_bfloat162 hA1 = *(__nv_bfloat162*)&ya1;
                __nv_bfloat162 hB1 = *(__nv_bfloat162*)&yb1;
                pf[c][0] = pack2_bf16(acc[0] * __bfloat162float(hA0.x), acc[1] * __bfloat162float(hA0.y));
                pf[c][1] = pack2_bf16(acc[2] * __bfloat162float(hB0.x), acc[3] * __bfloat162float(hB0.y));
                pf[c][2] = pack2_bf16(acc[4] * __bfloat162float(hA1.x), acc[5] * __bfloat162float(hA1.y));
                pf[c][3] = pack2_bf16(acc[6] * __bfloat162float(hB1.x), acc[7] * __bfloat162float(hB1.y));
            }
        }

        // ---- stage C: m = tanh(p @ Wc); reduce-add to out[dst] ----
        {
#pragma unroll
            for (int c = 0; c < 4; ++c) {
                float acc[8];
#pragma unroll
                for (int e = 0; e < 8; ++e) acc[e] = 0.f;
#pragma unroll
                for (int k = 0; k < 8; ++k) {
                    uint32_t b[4];
                    ldsm_x4t(wcc + (uint32_t)(k * 16 + krow) * STRIDE64 + (uint32_t)(c * 16 + xoff) * 2, b);
                    mma16816(acc + 0, pf[k], b + 0);
                    mma16816(acc + 4, pf[k], b + 2);
                }
                int col = c * 16 + q * 2;
                if (egA < E) {
                    float* p0 = out + (size_t)dA * 64 + col;
                    asm volatile("red.global.add.v2.f32 [%0], {%1,%2};"
                        :: "l"(p0), "f"(fast_tanh(acc[0])), "f"(fast_tanh(acc[1])) : "memory");
                    float* p1 = out + (size_t)dA * 64 + col + 8;
                    asm volatile("red.global.add.v2.f32 [%0], {%1,%2};"
                        :: "l"(p1), "f"(fast_tanh(acc[4])), "f"(fast_tanh(acc[5])) : "memory");
                }
                if (egB < E) {
                    float* p0 = out + (size_t)dB * 64 + col;
                    asm volatile("red.global.add.v2.f32 [%0], {%1,%2};"
                        :: "l"(p0), "f"(fast_tanh(acc[2])), "f"(fast_tanh(acc[3])) : "memory");
                    float* p1 = out + (size_t)dB * 64 + col + 8;
                    asm volatile("red.global.add.v2.f32 [%0], {%1,%2};"
                        :: "l"(p1), "f"(fast_tanh(acc[6])), "f"(fast_tanh(acc[7])) : "memory");
                }
            }
        }
    }
}

extern "C" void kernel_launch(void* const* d_in, const int* in_sizes, int n_in,
                              void* d_out, int out_size) {
    const float* h   = (const float*)d_in[0];
    const float* eh  = (const float*)d_in[1];
    const float* Wn1 = (const float*)d_in[2];
    const float* bn1 = (const float*)d_in[3];
    const float* Wn2 = (const float*)d_in[4];
    const float* We1 = (const float*)d_in[5];
    const float* be1 = (const float*)d_in[6];
    const float* We2 = (const float*)d_in[7];
    const float* Wc  = (const float*)d_in[8];
    const float* Wue = (const float*)d_in[9];
    const int*   src = (const int*)d_in[10];
    const int*   dst = (const int*)d_in[11];
    float* out = (float*)d_out;

    int E = in_sizes[10];
    int Nn = in_sizes[0] / 64;
    if (Nn > N_MAX) Nn = N_MAX;
    int nTiles = (E + M_TILE - 1) / M_TILE;

    convert_weights<<<(40960 + 255) / 256, 256>>>(Wue, We1, We2, Wc);

    cudaFuncSetAttribute(node_kernel, cudaFuncAttributeMaxDynamicSharedMemorySize, NSMEM_BYTES);
    node_kernel<<<(Nn + 127) / 128, NTHREADS, NSMEM_BYTES>>>(h, Wn1, bn1, Wn2, out, Nn);

    int nSM = 148;
    cudaDeviceGetAttribute(&nSM, cudaDevAttrMultiProcessorCount, 0);
    int grid = nSM;
    if (grid > nTiles) grid = nTiles;

    cudaFuncSetAttribute(edge_kernel, cudaFuncAttributeMaxDynamicSharedMemorySize, ESMEM_BYTES);
    edge_kernel<<<grid, ETHREADS, ESMEM_BYTES>>>(h, eh, be1, src, dst, out, E, nTiles);
}

// round 13
// speedup vs baseline: 1.0944x; 1.0944x over previous
#include <cuda_runtime.h>
#include <cuda_bf16.h>
#include <math.h>
#include <stdint.h>

#define ETHREADS 256
#define NTHREADS 256
#define M_TILE 128
#define N_MAX 50000

#define STRIDE128 272
#define STRIDE64  144

// ---- padded bf16 weight images ----
#define IWCB 0        // Wcomb [128x128] s272 : 34816
#define IWE2 34816    // We2   [128x128] s272 : 34816
#define IWC  69632    // Wc    [128x64]  s144 : 18432
#define IMG_TOTAL 88064
__device__ __align__(16) unsigned char g_wimg[IMG_TOTAL];

// per-node m1 table: Y1 = relu(h@Wn1+b1)@Wn2, bf16 [N_MAX x 128]
__device__ __align__(16) __nv_bfloat16 g_Y1[(size_t)N_MAX * 128];

// ---- edge kernel smem (bytes) ----
#define WBUF_OFF 0          // 34816 streamed weight
#define SA_OFF   34816      // 34816 A = [t | eh]
#define SX_OFF   69632      // 34816 x2 / p
#define SB2_OFF  104448     // 512
#define SSRC_OFF 104960     // 512
#define SDST_OFF 105472     // 512
#define ESMEM_BYTES 105984

// ---- node kernel smem ----
#define NW1_OFF 0
#define NW2_OFF (NW1_OFF + 64*STRIDE128)
#define NH_OFF  (NW2_OFF + 128*STRIDE128)
#define NX_OFF  (NH_OFF + 128*STRIDE64)
#define NB_OFF  (NX_OFF + 128*STRIDE128)
#define NSMEM_BYTES (NB_OFF + 512)

__device__ __forceinline__ uint32_t smem_u32(const void* p) {
    uint32_t a;
    asm("{ .reg .u64 t; cvta.to.shared.u64 t, %1; cvt.u32.u64 %0, t; }" : "=r"(a) : "l"(p));
    return a;
}
__device__ __forceinline__ uint32_t pack2_bf16(float a, float b) {
    __nv_bfloat162 p = __float22bfloat162_rn(make_float2(a, b));
    return *(unsigned int*)&p;
}
__device__ __forceinline__ uint2 pack4_bf16(float a, float b, float c, float d) {
    uint2 r; r.x = pack2_bf16(a, b); r.y = pack2_bf16(c, d); return r;
}
__device__ __forceinline__ float fast_tanh(float x) {
    float y;
    asm("tanh.approx.f32 %0, %1;" : "=f"(y) : "f"(x));
    return y;
}
__device__ __forceinline__ void ldsm_x4(uint32_t addr, uint32_t r[4]) {
    asm volatile("ldmatrix.sync.aligned.m8n8.x4.shared.b16 {%0,%1,%2,%3}, [%4];"
        : "=r"(r[0]), "=r"(r[1]), "=r"(r[2]), "=r"(r[3]) : "r"(addr));
}
__device__ __forceinline__ void ldsm_x4t(uint32_t addr, uint32_t r[4]) {
    asm volatile("ldmatrix.sync.aligned.m8n8.x4.trans.shared.b16 {%0,%1,%2,%3}, [%4];"
        : "=r"(r[0]), "=r"(r[1]), "=r"(r[2]), "=r"(r[3]) : "r"(addr));
}
__device__ __forceinline__ void mma16816(float d[4], const uint32_t a[4], const uint32_t b[2]) {
    asm volatile("mma.sync.aligned.m16n8k16.row.col.f32.bf16.bf16.f32 "
        "{%0,%1,%2,%3},{%4,%5,%6,%7},{%8,%9},{%0,%1,%2,%3};"
        : "+f"(d[0]), "+f"(d[1]), "+f"(d[2]), "+f"(d[3])
        : "r"(a[0]), "r"(a[1]), "r"(a[2]), "r"(a[3]), "r"(b[0]), "r"(b[1]));
}

// cp.async weight stream
__device__ __forceinline__ void cp_w(uint32_t sdst, int img_off, int bytes, int tid) {
    const unsigned char* gsrc = g_wimg + img_off;
    for (int i = tid * 16; i < bytes; i += ETHREADS * 16)
        asm volatile("cp.async.cg.shared.global [%0], [%1], 16;"
                     :: "r"(sdst + i), "l"(gsrc + i));
    asm volatile("cp.async.commit_group;");
}
#define CP_WAIT0() asm volatile("cp.async.wait_group 0;" ::: "memory")

// warp covers 64 rows (2 halves x 2 m16 tiles), B frags reused across halves
template<int KT, int NTH>
__device__ __forceinline__ void mma_stage2(uint32_t aAddr, int aStride,
                                           uint32_t wAddr, int wStride,
                                           int m0, int n0, int lane,
                                           float acc[2][2][NTH][4]) {
#pragma unroll
    for (int hf = 0; hf < 2; ++hf)
#pragma unroll
        for (int mt = 0; mt < 2; ++mt)
#pragma unroll
            for (int n = 0; n < NTH; ++n)
#pragma unroll
                for (int e = 0; e < 4; ++e) acc[hf][mt][n][e] = 0.f;
    const int krow = lane & 15;
    const int xoff = (lane >> 4) << 3;
#pragma unroll
    for (int k = 0; k < KT; ++k) {
        uint32_t b[NTH / 2][4];
#pragma unroll
        for (int np = 0; np < NTH / 2; ++np)
            ldsm_x4t(wAddr + (uint32_t)(k * 16 + krow) * wStride + (uint32_t)(n0 + np * 16 + xoff) * 2, b[np]);
#pragma unroll
        for (int hf = 0; hf < 2; ++hf) {
            uint32_t a[2][4];
#pragma unroll
            for (int mt = 0; mt < 2; ++mt)
                ldsm_x4(aAddr + (uint32_t)(m0 + hf * 32 + mt * 16 + krow) * aStride + (uint32_t)(k * 16 + xoff) * 2, a[mt]);
#pragma unroll
            for (int np = 0; np < NTH / 2; ++np) {
                mma16816(acc[hf][0][np * 2 + 0], a[0], b[np] + 0);
                mma16816(acc[hf][1][np * 2 + 0], a[1], b[np] + 0);
                mma16816(acc[hf][0][np * 2 + 1], a[0], b[np] + 2);
                mma16816(acc[hf][1][np * 2 + 1], a[1], b[np] + 2);
            }
        }
    }
}

// single-strip version: warp covers 32 rows (2 m16 tiles) x NTH*8 cols
template<int KT, int NTH>
__device__ __forceinline__ void mma_stage(uint32_t aAddr, int aStride,
                                          uint32_t wAddr, int wStride,
                                          int m0, int n0, int lane,
                                          float acc[2][NTH][4]) {
#pragma unroll
    for (int mt = 0; mt < 2; ++mt)
#pragma unroll
        for (int n = 0; n < NTH; ++n)
#pragma unroll
            for (int e = 0; e < 4; ++e) acc[mt][n][e] = 0.f;
    const int krow = lane & 15;
    const int xoff = (lane >> 4) << 3;
#pragma unroll
    for (int k = 0; k < KT; ++k) {
        uint32_t a[2][4];
#pragma unroll
        for (int mt = 0; mt < 2; ++mt)
            ldsm_x4(aAddr + (uint32_t)(m0 + mt * 16 + krow) * aStride + (uint32_t)(k * 16 + xoff) * 2, a[mt]);
#pragma unroll
        for (int np = 0; np < NTH / 2; ++np) {
            uint32_t b[4];
            ldsm_x4t(wAddr + (uint32_t)(k * 16 + krow) * wStride + (uint32_t)(n0 + np * 16 + xoff) * 2, b);
            mma16816(acc[0][np * 2 + 0], a[0], b + 0);
            mma16816(acc[1][np * 2 + 0], a[1], b + 0);
            mma16816(acc[0][np * 2 + 1], a[0], b + 2);
            mma16816(acc[1][np * 2 + 1], a[1], b + 2);
        }
    }
}

__device__ __forceinline__ void load_weight_smem(char* smemc, int off, const float* __restrict__ W,
                                                 int K, int N, int stride, int tid, int nthr) {
    int n4 = (K * N) >> 2;
    for (int i = tid; i < n4; i += nthr) {
        int idx = i << 2;
        int r = idx / N, c = idx % N;
        float4 v = *(const float4*)(W + idx);
        *(uint2*)(smemc + off + r * stride + c * 2) = pack4_bf16(v.x, v.y, v.z, v.w);
    }
}

// build Wcomb = [[0.2*Wue@We1],[0.8*We1]] (fp32 accum) + We2 + Wc images
__global__ void convert_weights(const float* __restrict__ Wue, const float* __restrict__ We1,
                                const float* __restrict__ We2, const float* __restrict__ Wc) {
    int i = blockIdx.x * blockDim.x + threadIdx.x;
    if (i < 16384) {                // Wcomb 128x128 s272
        int r = i >> 7, c = i & 127;
        float v;
        if (r < 64) {
            float s = 0.f;
#pragma unroll 8
            for (int k = 0; k < 64; ++k) s += Wue[r * 64 + k] * We1[k * 128 + c];
            v = 0.2f * s;
        } else {
            v = 0.8f * We1[(r - 64) * 128 + c];
        }
        *(__nv_bfloat16*)(g_wimg + IWCB + r * STRIDE128 + c * 2) = __float2bfloat16(v);
    } else if (i < 32768) {         // We2 128x128 s272
        int j = i - 16384, r = j >> 7, c = j & 127;
        *(__nv_bfloat16*)(g_wimg + IWE2 + r * STRIDE128 + c * 2) = __float2bfloat16(We2[j]);
    } else if (i < 40960) {         // Wc 128x64 s144
        int j = i - 32768, r = j >> 6, c = j & 63;
        *(__nv_bfloat16*)(g_wimg + IWC + r * STRIDE64 + c * 2) = __float2bfloat16(Wc[j]);
    }
}

// =============== node kernel: Y1 table + out = h (residual init) ===============
__global__ __launch_bounds__(NTHREADS)
void node_kernel(const float* __restrict__ h,
                 const float* __restrict__ Wn1, const float* __restrict__ bn1,
                 const float* __restrict__ Wn2, float* __restrict__ out, int Nn)
{
    extern __shared__ char smem[];
    const uint32_t sbase = smem_u32(smem);
    const int tid = threadIdx.x;
    const int warp = tid >> 5;
    const int lane = tid & 31;
    const int mi = warp >> 1, nj = warp & 1;
    const int m0 = mi * 32, n0 = nj * 64;
    const int g = lane >> 2, q = lane & 3;
    const int r0 = blockIdx.x * 128;

    float* sB = (float*)(smem + NB_OFF);
    load_weight_smem(smem, NW1_OFF, Wn1, 64, 128, STRIDE128, tid, NTHREADS);
    load_weight_smem(smem, NW2_OFF, Wn2, 128, 128, STRIDE128, tid, NTHREADS);
    if (tid < 128) sB[tid] = bn1[tid];

    for (int i = tid; i < 128 * 16; i += NTHREADS) {
        int r = i >> 4, d4 = i & 15;
        int nr = r0 + r;
        bool valid = (nr < Nn);
        if (!valid) nr = Nn - 1;
        float4 v = ((const float4*)(h + (size_t)nr * 64))[d4];
        if (valid) ((float4*)(out + (size_t)nr * 64))[d4] = v;
        *(uint2*)(smem + NH_OFF + r * STRIDE64 + d4 * 8) = pack4_bf16(v.x, v.y, v.z, v.w);
    }
    __syncthreads();

    float acc[2][8][4];
    mma_stage<4, 8>(sbase + NH_OFF, STRIDE64, sbase + NW1_OFF, STRIDE128, m0, n0, lane, acc);
#pragma unroll
    for (int mt = 0; mt < 2; ++mt)
#pragma unroll
        for (int n = 0; n < 8; ++n) {
            int col = n0 + n * 8 + q * 2;
            float b0 = sB[col], b1 = sB[col + 1];
            int rA = m0 + mt * 16 + g;
            *(uint32_t*)(smem + NX_OFF + rA * STRIDE128 + col * 2) =
                pack2_bf16(fmaxf(acc[mt][n][0] + b0, 0.f), fmaxf(acc[mt][n][1] + b1, 0.f));
            *(uint32_t*)(smem + NX_OFF + (rA + 8) * STRIDE128 + col * 2) =
                pack2_bf16(fmaxf(acc[mt][n][2] + b0, 0.f), fmaxf(acc[mt][n][3] + b1, 0.f));
        }
    __syncthreads();

    mma_stage<8, 8>(sbase + NX_OFF, STRIDE128, sbase + NW2_OFF, STRIDE128, m0, n0, lane, acc);
#pragma unroll
    for (int mt = 0; mt < 2; ++mt)
#pragma unroll
        for (int n = 0; n < 8; ++n) {
            int col = n0 + n * 8 + q * 2;
            int rA = m0 + mt * 16 + g;
            int nrA = r0 + rA, nrB = r0 + rA + 8;
            if (nrA < Nn)
                *(uint32_t*)(g_Y1 + (size_t)nrA * 128 + col) = pack2_bf16(acc[mt][n][0], acc[mt][n][1]);
            if (nrB < Nn)
                *(uint32_t*)(g_Y1 + (size_t)nrB * 128 + col) = pack2_bf16(acc[mt][n][2], acc[mt][n][3]);
        }
}

// =============== edge kernel: 2 CTAs/SM, streamed weights, batched gather ===============
__global__ __launch_bounds__(ETHREADS, 2)
void edge_kernel(const float* __restrict__ h, const float* __restrict__ eh,
                 const float* __restrict__ be1,
                 const int* __restrict__ src, const int* __restrict__ dst,
                 float* __restrict__ out, int E, int nTiles)
{
    extern __shared__ char smem[];
    const uint32_t sbase = smem_u32(smem);
    const int tid = threadIdx.x;
    const int warp = tid >> 5;
    const int lane = tid & 31;

    // stages A/B: 2 M-strips (64 rows) x 4 N-quarters
    const int mi = warp >> 2;
    const int nj = warp & 3;
    const int m0 = mi * 64;
    const int n0w = nj * 32;   // N=128 (NTH=4)
    // stage C remap: 4 M-strips (32 rows) x 2 N-halves (32 cols, NTH=4)
    const int m0c = (warp & 3) * 32;
    const int n0c = (warp >> 2) * 32;
    const int g = lane >> 2, q = lane & 3;

    float* sB2 = (float*)(smem + SB2_OFF);
    int* sSrc = (int*)(smem + SSRC_OFF);
    int* sDst = (int*)(smem + SDST_OFF);

    if (tid < 128) sB2[tid] = be1[tid];

    // prefetch first tile's indices
    int nxt_s = 0, nxt_d = 0;
    if (tid < M_TILE) {
        long e = (long)blockIdx.x * M_TILE + tid;
        int eg = (e < E) ? (int)e : E - 1;
        nxt_s = src[eg]; nxt_d = dst[eg];
    }

    for (int tile = blockIdx.x; tile < nTiles; tile += gridDim.x) {
        const int e0 = tile * M_TILE;
        __syncthreads();   // [1] prev tile fully done

        if (tid < M_TILE) { sSrc[tid] = nxt_s; sDst[tid] = nxt_d; }
        cp_w(sbase + WBUF_OFF, IWCB, 34816, tid);   // Wcomb stream (overlaps gather)
        __syncthreads();   // [2] indices visible

        if (tid < M_TILE) {
            long ne = (long)(tile + gridDim.x) * M_TILE + tid;
            int eg = (ne < E) ? (int)ne : E - 1;
            nxt_s = src[eg]; nxt_d = dst[eg];
        }

        // gather: A = [ t = hs*hd | eh ]; batched loads for high MLP
#pragma unroll
        for (int c = 0; c < 2; ++c) {
            float4 va[4], vb[4], ve[4];
#pragma unroll
            for (int j = 0; j < 4; ++j) {
                int i = tid + (c * 4 + j) * ETHREADS;
                int e = i >> 4, d4 = i & 15;
                int eg = e0 + e; if (eg >= E) eg = E - 1;
                va[j] = ((const float4*)(h + (size_t)sSrc[e] * 64))[d4];
                vb[j] = ((const float4*)(h + (size_t)sDst[e] * 64))[d4];
                ve[j] = ((const float4*)(eh + (size_t)eg * 64))[d4];
            }
#pragma unroll
            for (int j = 0; j < 4; ++j) {
                int i = tid + (c * 4 + j) * ETHREADS;
                int e = i >> 4, d4 = i & 15;
                *(uint2*)(smem + SA_OFF + e * STRIDE128 + d4 * 8) =
                    pack4_bf16(va[j].x * vb[j].x, va[j].y * vb[j].y,
                               va[j].z * vb[j].z, va[j].w * vb[j].w);
                *(uint2*)(smem + SA_OFF + e * STRIDE128 + 128 + d4 * 8) =
                    pack4_bf16(ve[j].x, ve[j].y, ve[j].z, ve[j].w);
            }
        }
        CP_WAIT0();
        __syncthreads();   // [3] A + Wcomb ready

        // ---- stage A: x2 = relu(A @ Wcomb + b2) -> SX ----
        {
            float acc[2][2][4][4];
            mma_stage2<8, 4>(sbase + SA_OFF, STRIDE128, sbase + WBUF_OFF, STRIDE128, m0, n0w, lane, acc);
            __syncthreads();   // [4] Wcomb reads done
            cp_w(sbase + WBUF_OFF, IWE2, 34816, tid);   // We2 stream (overlaps epilogue)
#pragma unroll
            for (int hf = 0; hf < 2; ++hf)
#pragma unroll
                for (int mt = 0; mt < 2; ++mt)
#pragma unroll
                    for (int n = 0; n < 4; ++n) {
                        int col = n0w + n * 8 + q * 2;
                        float b0 = sB2[col], b1 = sB2[col + 1];
                        int rA = m0 + hf * 32 + mt * 16 + g;
                        *(uint32_t*)(smem + SX_OFF + rA * STRIDE128 + col * 2) =
                            pack2_bf16(fmaxf(acc[hf][mt][n][0] + b0, 0.f), fmaxf(acc[hf][mt][n][1] + b1, 0.f));
                        *(uint32_t*)(smem + SX_OFF + (rA + 8) * STRIDE128 + col * 2) =
                            pack2_bf16(fmaxf(acc[hf][mt][n][2] + b0, 0.f), fmaxf(acc[hf][mt][n][3] + b1, 0.f));
                    }
        }
        CP_WAIT0();
        __syncthreads();   // [5] x2 + We2 ready

        // ---- stage B: p = Y1[src] * (x2 @ We2) -> SA (A dead) ----
        {
            uint32_t ym[2][2][4][2];
#pragma unroll
            for (int hf = 0; hf < 2; ++hf)
#pragma unroll
                for (int mt = 0; mt < 2; ++mt)
#pragma unroll
                    for (int n = 0; n < 4; ++n) {
                        int col = n0w + n * 8 + q * 2;
                        int rA = m0 + hf * 32 + mt * 16 + g;
                        ym[hf][mt][n][0] = *(const uint32_t*)(g_Y1 + (size_t)sSrc[rA] * 128 + col);
                        ym[hf][mt][n][1] = *(const uint32_t*)(g_Y1 + (size_t)sSrc[rA + 8] * 128 + col);
                    }
            float acc[2][2][4][4];
            mma_stage2<8, 4>(sbase + SX_OFF, STRIDE128, sbase + WBUF_OFF, STRIDE128, m0, n0w, lane, acc);
            __syncthreads();   // [6] We2 reads done
            cp_w(sbase + WBUF_OFF, IWC, 18432, tid);    // Wc stream (overlaps epilogue)
#pragma unroll
            for (int hf = 0; hf < 2; ++hf)
#pragma unroll
                for (int mt = 0; mt < 2; ++mt)
#pragma unroll
                    for (int n = 0; n < 4; ++n) {
                        int col = n0w + n * 8 + q * 2;
                        int rA = m0 + hf * 32 + mt * 16 + g;
                        __nv_bfloat162 hA = *(__nv_bfloat162*)&ym[hf][mt][n][0];
                        __nv_bfloat162 hB = *(__nv_bfloat162*)&ym[hf][mt][n][1];
                        *(uint32_t*)(smem + SA_OFF + rA * STRIDE128 + col * 2) =
                            pack2_bf16(acc[hf][mt][n][0] * __bfloat162float(hA.x),
                                       acc[hf][mt][n][1] * __bfloat162float(hA.y));
                        *(uint32_t*)(smem + SA_OFF + (rA + 8) * STRIDE128 + col * 2) =
                            pack2_bf16(acc[hf][mt][n][2] * __bfloat162float(hB.x),
                                       acc[hf][mt][n][3] * __bfloat162float(hB.y));
                    }
        }
        CP_WAIT0();
        __syncthreads();   // [7] p + Wc ready

        // ---- stage C (remapped 4Mx2N): m = tanh(p @ Wc); reduce-add to out[dst] ----
        {
            float a6[2][4][4];
            mma_stage<8, 4>(sbase + SA_OFF, STRIDE128, sbase + WBUF_OFF, STRIDE64, m0c, n0c, lane, a6);
#pragma unroll
            for (int mt = 0; mt < 2; ++mt) {
                int rA = m0c + mt * 16 + g;
                int rB = rA + 8;
                int egA = e0 + rA, egB = e0 + rB;
                int dA = sDst[rA], dB = sDst[rB];
#pragma unroll
                for (int n = 0; n < 4; ++n) {
                    int col = n0c + n * 8 + q * 2;
                    if (egA < E) {
                        float* p = out + (size_t)dA * 64 + col;
                        asm volatile("red.global.add.v2.f32 [%0], {%1,%2};"
                            :: "l"(p), "f"(fast_tanh(a6[mt][n][0])), "f"(fast_tanh(a6[mt][n][1])) : "memory");
                    }
                    if (egB < E) {
                        float* p = out + (size_t)dB * 64 + col;
                        asm volatile("red.global.add.v2.f32 [%0], {%1,%2};"
                            :: "l"(p), "f"(fast_tanh(a6[mt][n][2])), "f"(fast_tanh(a6[mt][n][3])) : "memory");
                    }
                }
            }
        }
    }
}

extern "C" void kernel_launch(void* const* d_in, const int* in_sizes, int n_in,
                              void* d_out, int out_size) {
    const float* h   = (const float*)d_in[0];
    const float* eh  = (const float*)d_in[1];
    const float* Wn1 = (const float*)d_in[2];
    const float* bn1 = (const float*)d_in[3];
    const float* Wn2 = (const float*)d_in[4];
    const float* We1 = (const float*)d_in[5];
    const float* be1 = (const float*)d_in[6];
    const float* We2 = (const float*)d_in[7];
    const float* Wc  = (const float*)d_in[8];
    const float* Wue = (const float*)d_in[9];
    const int*   src = (const int*)d_in[10];
    const int*   dst = (const int*)d_in[11];
    float* out = (float*)d_out;

    int E = in_sizes[10];
    int Nn = in_sizes[0] / 64;
    if (Nn > N_MAX) Nn = N_MAX;
    int nTiles = (E + M_TILE - 1) / M_TILE;

    convert_weights<<<(40960 + 255) / 256, 256>>>(Wue, We1, We2, Wc);

    cudaFuncSetAttribute(node_kernel, cudaFuncAttributeMaxDynamicSharedMemorySize, NSMEM_BYTES);
    node_kernel<<<(Nn + 127) / 128, NTHREADS, NSMEM_BYTES>>>(h, Wn1, bn1, Wn2, out, Nn);

    int nSM = 148;
    cudaDeviceGetAttribute(&nSM, cudaDevAttrMultiProcessorCount, 0);
    int grid = 2 * nSM;
    if (grid > nTiles) grid = nTiles;

    cudaFuncSetAttribute(edge_kernel, cudaFuncAttributeMaxDynamicSharedMemorySize, ESMEM_BYTES);
    edge_kernel<<<grid, ETHREADS, ESMEM_BYTES>>>(h, eh, be1, src, dst, out, E, nTiles);
}

// round 14
// speedup vs baseline: 1.1028x; 1.0077x over previous
#include <cuda_runtime.h>
#include <cuda_bf16.h>
#include <math.h>
#include <stdint.h>

#define ETHREADS 256
#define NTHREADS 256
#define M_TILE 128
#define N_MAX 50000

#define STRIDE128 272
#define STRIDE64  144

// ---- padded bf16 weight images ----
#define IWCB 0        // Wcomb [128x128] s272 : 34816
#define IWE2 34816    // We2   [128x128] s272 : 34816
#define IWC  69632    // Wc    [128x64]  s144 : 18432
#define IMG_TOTAL 88064
__device__ __align__(16) unsigned char g_wimg[IMG_TOTAL];

// per-node m1 table: Y1 = relu(h@Wn1+b1)@Wn2, bf16 [N_MAX x 128]
__device__ __align__(16) __nv_bfloat16 g_Y1[(size_t)N_MAX * 128];

// dynamic tile ticket (reset by cudaMemsetAsync each launch)
__device__ int g_ticket;

// ---- edge kernel smem (bytes) ----
#define WBUF_OFF 0          // 34816 streamed weight
#define SA_OFF   34816      // 34816 A = [t | eh] -> p
#define SX_OFF   69632      // 34816 x2
#define SB2_OFF  104448     // 512
#define SSRC_OFF 104960     // 512
#define SDST_OFF 105472     // 512
#define STILE_OFF 105984    // 16
#define ESMEM_BYTES 106000

// ---- node kernel smem ----
#define NW1_OFF 0
#define NW2_OFF (NW1_OFF + 64*STRIDE128)
#define NH_OFF  (NW2_OFF + 128*STRIDE128)
#define NX_OFF  (NH_OFF + 128*STRIDE64)
#define NB_OFF  (NX_OFF + 128*STRIDE128)
#define NSMEM_BYTES (NB_OFF + 512)

__device__ __forceinline__ uint32_t smem_u32(const void* p) {
    uint32_t a;
    asm("{ .reg .u64 t; cvta.to.shared.u64 t, %1; cvt.u32.u64 %0, t; }" : "=r"(a) : "l"(p));
    return a;
}
__device__ __forceinline__ uint32_t pack2_bf16(float a, float b) {
    __nv_bfloat162 p = __float22bfloat162_rn(make_float2(a, b));
    return *(unsigned int*)&p;
}
__device__ __forceinline__ uint2 pack4_bf16(float a, float b, float c, float d) {
    uint2 r; r.x = pack2_bf16(a, b); r.y = pack2_bf16(c, d); return r;
}
__device__ __forceinline__ float fast_tanh(float x) {
    float y;
    asm("tanh.approx.f32 %0, %1;" : "=f"(y) : "f"(x));
    return y;
}
__device__ __forceinline__ void ldsm_x4(uint32_t addr, uint32_t r[4]) {
    asm volatile("ldmatrix.sync.aligned.m8n8.x4.shared.b16 {%0,%1,%2,%3}, [%4];"
        : "=r"(r[0]), "=r"(r[1]), "=r"(r[2]), "=r"(r[3]) : "r"(addr));
}
__device__ __forceinline__ void ldsm_x4t(uint32_t addr, uint32_t r[4]) {
    asm volatile("ldmatrix.sync.aligned.m8n8.x4.trans.shared.b16 {%0,%1,%2,%3}, [%4];"
        : "=r"(r[0]), "=r"(r[1]), "=r"(r[2]), "=r"(r[3]) : "r"(addr));
}
__device__ __forceinline__ void mma16816(float d[4], const uint32_t a[4], const uint32_t b[2]) {
    asm volatile("mma.sync.aligned.m16n8k16.row.col.f32.bf16.bf16.f32 "
        "{%0,%1,%2,%3},{%4,%5,%6,%7},{%8,%9},{%0,%1,%2,%3};"
        : "+f"(d[0]), "+f"(d[1]), "+f"(d[2]), "+f"(d[3])
        : "r"(a[0]), "r"(a[1]), "r"(a[2]), "r"(a[3]), "r"(b[0]), "r"(b[1]));
}

// cp.async weight stream
__device__ __forceinline__ void cp_w(uint32_t sdst, int img_off, int bytes, int tid) {
    const unsigned char* gsrc = g_wimg + img_off;
    for (int i = tid * 16; i < bytes; i += ETHREADS * 16)
        asm volatile("cp.async.cg.shared.global [%0], [%1], 16;"
                     :: "r"(sdst + i), "l"(gsrc + i));
    asm volatile("cp.async.commit_group;");
}
#define CP_WAIT0() asm volatile("cp.async.wait_group 0;" ::: "memory")

// warp covers 64 rows (2 halves x 2 m16 tiles), B frags reused across halves
template<int KT, int NTH>
__device__ __forceinline__ void mma_stage2(uint32_t aAddr, int aStride,
                                           uint32_t wAddr, int wStride,
                                           int m0, int n0, int lane,
                                           float acc[2][2][NTH][4]) {
#pragma unroll
    for (int hf = 0; hf < 2; ++hf)
#pragma unroll
        for (int mt = 0; mt < 2; ++mt)
#pragma unroll
            for (int n = 0; n < NTH; ++n)
#pragma unroll
                for (int e = 0; e < 4; ++e) acc[hf][mt][n][e] = 0.f;
    const int krow = lane & 15;
    const int xoff = (lane >> 4) << 3;
#pragma unroll
    for (int k = 0; k < KT; ++k) {
        uint32_t b[NTH / 2][4];
#pragma unroll
        for (int np = 0; np < NTH / 2; ++np)
            ldsm_x4t(wAddr + (uint32_t)(k * 16 + krow) * wStride + (uint32_t)(n0 + np * 16 + xoff) * 2, b[np]);
#pragma unroll
        for (int hf = 0; hf < 2; ++hf) {
            uint32_t a[2][4];
#pragma unroll
            for (int mt = 0; mt < 2; ++mt)
                ldsm_x4(aAddr + (uint32_t)(m0 + hf * 32 + mt * 16 + krow) * aStride + (uint32_t)(k * 16 + xoff) * 2, a[mt]);
#pragma unroll
            for (int np = 0; np < NTH / 2; ++np) {
                mma16816(acc[hf][0][np * 2 + 0], a[0], b[np] + 0);
                mma16816(acc[hf][1][np * 2 + 0], a[1], b[np] + 0);
                mma16816(acc[hf][0][np * 2 + 1], a[0], b[np] + 2);
                mma16816(acc[hf][1][np * 2 + 1], a[1], b[np] + 2);
            }
        }
    }
}

// single-strip version: warp covers 32 rows (2 m16 tiles) x NTH*8 cols
template<int KT, int NTH>
__device__ __forceinline__ void mma_stage(uint32_t aAddr, int aStride,
                                          uint32_t wAddr, int wStride,
                                          int m0, int n0, int lane,
                                          float acc[2][NTH][4]) {
#pragma unroll
    for (int mt = 0; mt < 2; ++mt)
#pragma unroll
        for (int n = 0; n < NTH; ++n)
#pragma unroll
            for (int e = 0; e < 4; ++e) acc[mt][n][e] = 0.f;
    const int krow = lane & 15;
    const int xoff = (lane >> 4) << 3;
#pragma unroll
    for (int k = 0; k < KT; ++k) {
        uint32_t a[2][4];
#pragma unroll
        for (int mt = 0; mt < 2; ++mt)
            ldsm_x4(aAddr + (uint32_t)(m0 + mt * 16 + krow) * aStride + (uint32_t)(k * 16 + xoff) * 2, a[mt]);
#pragma unroll
        for (int np = 0; np < NTH / 2; ++np) {
            uint32_t b[4];
            ldsm_x4t(wAddr + (uint32_t)(k * 16 + krow) * wStride + (uint32_t)(n0 + np * 16 + xoff) * 2, b);
            mma16816(acc[0][np * 2 + 0], a[0], b + 0);
            mma16816(acc[1][np * 2 + 0], a[1], b + 0);
            mma16816(acc[0][np * 2 + 1], a[0], b + 2);
            mma16816(acc[1][np * 2 + 1], a[1], b + 2);
        }
    }
}

__device__ __forceinline__ void load_weight_smem(char* smemc, int off, const float* __restrict__ W,
                                                 int K, int N, int stride, int tid, int nthr) {
    int n4 = (K * N) >> 2;
    for (int i = tid; i < n4; i += nthr) {
        int idx = i << 2;
        int r = idx / N, c = idx % N;
        float4 v = *(const float4*)(W + idx);
        *(uint2*)(smemc + off + r * stride + c * 2) = pack4_bf16(v.x, v.y, v.z, v.w);
    }
}

// =============== node kernel: Y1 table + residual init + weight conversion ===============
// blocks [0, nNodeBlocks): node MLP; blocks [nNodeBlocks, +160): weight image build
__global__ __launch_bounds__(NTHREADS)
void node_kernel(const float* __restrict__ h,
                 const float* __restrict__ Wn1, const float* __restrict__ bn1,
                 const float* __restrict__ Wn2,
                 const float* __restrict__ Wue, const float* __restrict__ We1,
                 const float* __restrict__ We2, const float* __restrict__ Wc,
                 float* __restrict__ out, int Nn, int nNodeBlocks)
{
    if (blockIdx.x >= nNodeBlocks) {
        // ---- weight conversion part ----
        int i = (blockIdx.x - nNodeBlocks) * NTHREADS + threadIdx.x;
        if (i < 16384) {                // Wcomb 128x128 s272 = [[0.2*Wue@We1],[0.8*We1]]
            int r = i >> 7, c = i & 127;
            float v;
            if (r < 64) {
                float s = 0.f;
#pragma unroll 8
                for (int k = 0; k < 64; ++k) s += Wue[r * 64 + k] * We1[k * 128 + c];
                v = 0.2f * s;
            } else {
                v = 0.8f * We1[(r - 64) * 128 + c];
            }
            *(__nv_bfloat16*)(g_wimg + IWCB + r * STRIDE128 + c * 2) = __float2bfloat16(v);
        } else if (i < 32768) {         // We2 128x128 s272
            int j = i - 16384, r = j >> 7, c = j & 127;
            *(__nv_bfloat16*)(g_wimg + IWE2 + r * STRIDE128 + c * 2) = __float2bfloat16(We2[j]);
        } else if (i < 40960) {         // Wc 128x64 s144
            int j = i - 32768, r = j >> 6, c = j & 63;
            *(__nv_bfloat16*)(g_wimg + IWC + r * STRIDE64 + c * 2) = __float2bfloat16(Wc[j]);
        }
        return;
    }

    extern __shared__ char smem[];
    const uint32_t sbase = smem_u32(smem);
    const int tid = threadIdx.x;
    const int warp = tid >> 5;
    const int lane = tid & 31;
    const int mi = warp >> 1, nj = warp & 1;
    const int m0 = mi * 32, n0 = nj * 64;
    const int g = lane >> 2, q = lane & 3;
    const int r0 = blockIdx.x * 128;

    float* sB = (float*)(smem + NB_OFF);
    load_weight_smem(smem, NW1_OFF, Wn1, 64, 128, STRIDE128, tid, NTHREADS);
    load_weight_smem(smem, NW2_OFF, Wn2, 128, 128, STRIDE128, tid, NTHREADS);
    if (tid < 128) sB[tid] = bn1[tid];

    for (int i = tid; i < 128 * 16; i += NTHREADS) {
        int r = i >> 4, d4 = i & 15;
        int nr = r0 + r;
        bool valid = (nr < Nn);
        if (!valid) nr = Nn - 1;
        float4 v = ((const float4*)(h + (size_t)nr * 64))[d4];
        if (valid) ((float4*)(out + (size_t)nr * 64))[d4] = v;
        *(uint2*)(smem + NH_OFF + r * STRIDE64 + d4 * 8) = pack4_bf16(v.x, v.y, v.z, v.w);
    }
    __syncthreads();

    float acc[2][8][4];
    mma_stage<4, 8>(sbase + NH_OFF, STRIDE64, sbase + NW1_OFF, STRIDE128, m0, n0, lane, acc);
#pragma unroll
    for (int mt = 0; mt < 2; ++mt)
#pragma unroll
        for (int n = 0; n < 8; ++n) {
            int col = n0 + n * 8 + q * 2;
            float b0 = sB[col], b1 = sB[col + 1];
            int rA = m0 + mt * 16 + g;
            *(uint32_t*)(smem + NX_OFF + rA * STRIDE128 + col * 2) =
                pack2_bf16(fmaxf(acc[mt][n][0] + b0, 0.f), fmaxf(acc[mt][n][1] + b1, 0.f));
            *(uint32_t*)(smem + NX_OFF + (rA + 8) * STRIDE128 + col * 2) =
                pack2_bf16(fmaxf(acc[mt][n][2] + b0, 0.f), fmaxf(acc[mt][n][3] + b1, 0.f));
        }
    __syncthreads();

    mma_stage<8, 8>(sbase + NX_OFF, STRIDE128, sbase + NW2_OFF, STRIDE128, m0, n0, lane, acc);
#pragma unroll
    for (int mt = 0; mt < 2; ++mt)
#pragma unroll
        for (int n = 0; n < 8; ++n) {
            int col = n0 + n * 8 + q * 2;
            int rA = m0 + mt * 16 + g;
            int nrA = r0 + rA, nrB = r0 + rA + 8;
            if (nrA < Nn)
                *(uint32_t*)(g_Y1 + (size_t)nrA * 128 + col) = pack2_bf16(acc[mt][n][0], acc[mt][n][1]);
            if (nrB < Nn)
                *(uint32_t*)(g_Y1 + (size_t)nrB * 128 + col) = pack2_bf16(acc[mt][n][2], acc[mt][n][3]);
        }
}

// =============== edge kernel: 2 CTAs/SM, dynamic tiles, 6 barriers/tile ===============
__global__ __launch_bounds__(ETHREADS, 2)
void edge_kernel(const float* __restrict__ h, const float* __restrict__ eh,
                 const float* __restrict__ be1,
                 const int* __restrict__ src, const int* __restrict__ dst,
                 float* __restrict__ out, int E, int nTiles)
{
    extern __shared__ char smem[];
    const uint32_t sbase = smem_u32(smem);
    const int tid = threadIdx.x;
    const int warp = tid >> 5;
    const int lane = tid & 31;

    // stages A/B: 2 M-strips (64 rows) x 4 N-quarters
    const int mi = warp >> 2;
    const int nj = warp & 3;
    const int m0 = mi * 64;
    const int n0w = nj * 32;   // N=128 (NTH=4)
    // stage C remap: 4 M-strips (32 rows) x 2 N-halves
    const int m0c = (warp & 3) * 32;
    const int n0c = (warp >> 2) * 32;
    const int g = lane >> 2, q = lane & 3;

    float* sB2 = (float*)(smem + SB2_OFF);
    int* sSrc = (int*)(smem + SSRC_OFF);
    int* sDst = (int*)(smem + SDST_OFF);
    int* sTile = (int*)(smem + STILE_OFF);

    if (tid < 128) sB2[tid] = be1[tid];

    // prologue: first ticket + first Wcomb stream
    if (tid == 0) sTile[0] = atomicAdd(&g_ticket, 1);
    cp_w(sbase + WBUF_OFF, IWCB, 34816, tid);
    __syncthreads();
    int tile = sTile[0];

    while (tile < nTiles) {
        const int e0 = tile * M_TILE;

        // idx -> smem (for ym / stage-C preload) + gather with direct broadcast LDG
        if (tid < M_TILE) {
            int eg = e0 + tid; if (eg >= E) eg = E - 1;
            sSrc[tid] = src[eg];
            sDst[tid] = dst[eg];
        }
#pragma unroll
        for (int c = 0; c < 2; ++c) {
            int ss[4], dd[4];
            float4 va[4], vb[4], ve[4];
#pragma unroll
            for (int j = 0; j < 4; ++j) {
                int i = tid + (c * 4 + j) * ETHREADS;
                int e = i >> 4;
                int eg = e0 + e; if (eg >= E) eg = E - 1;
                ss[j] = src[eg]; dd[j] = dst[eg];
            }
#pragma unroll
            for (int j = 0; j < 4; ++j) {
                int i = tid + (c * 4 + j) * ETHREADS;
                int d4 = i & 15;
                int eg = e0 + (i >> 4); if (eg >= E) eg = E - 1;
                va[j] = ((const float4*)(h + (size_t)ss[j] * 64))[d4];
                vb[j] = ((const float4*)(h + (size_t)dd[j] * 64))[d4];
                ve[j] = ((const float4*)(eh + (size_t)eg * 64))[d4];
            }
#pragma unroll
            for (int j = 0; j < 4; ++j) {
                int i = tid + (c * 4 + j) * ETHREADS;
                int e = i >> 4, d4 = i & 15;
                *(uint2*)(smem + SA_OFF + e * STRIDE128 + d4 * 8) =
                    pack4_bf16(va[j].x * vb[j].x, va[j].y * vb[j].y,
                               va[j].z * vb[j].z, va[j].w * vb[j].w);
                *(uint2*)(smem + SA_OFF + e * STRIDE128 + 128 + d4 * 8) =
                    pack4_bf16(ve[j].x, ve[j].y, ve[j].z, ve[j].w);
            }
        }
        CP_WAIT0();
        __syncthreads();   // [3] A + idx + Wcomb ready

        // ---- stage A: x2 = relu(A @ Wcomb + b2) -> SX ----
        {
            float acc[2][2][4][4];
            mma_stage2<8, 4>(sbase + SA_OFF, STRIDE128, sbase + WBUF_OFF, STRIDE128, m0, n0w, lane, acc);
            __syncthreads();   // [4] Wcomb reads done
            cp_w(sbase + WBUF_OFF, IWE2, 34816, tid);   // We2 (overlaps epilogue)
#pragma unroll
            for (int hf = 0; hf < 2; ++hf)
#pragma unroll
                for (int mt = 0; mt < 2; ++mt)
#pragma unroll
                    for (int n = 0; n < 4; ++n) {
                        int col = n0w + n * 8 + q * 2;
                        float b0 = sB2[col], b1 = sB2[col + 1];
                        int rA = m0 + hf * 32 + mt * 16 + g;
                        *(uint32_t*)(smem + SX_OFF + rA * STRIDE128 + col * 2) =
                            pack2_bf16(fmaxf(acc[hf][mt][n][0] + b0, 0.f), fmaxf(acc[hf][mt][n][1] + b1, 0.f));
                        *(uint32_t*)(smem + SX_OFF + (rA + 8) * STRIDE128 + col * 2) =
                            pack2_bf16(fmaxf(acc[hf][mt][n][2] + b0, 0.f), fmaxf(acc[hf][mt][n][3] + b1, 0.f));
                    }
        }
        CP_WAIT0();
        __syncthreads();   // [5] x2 + We2 ready

        // ---- stage B: p = Y1[src] * (x2 @ We2) -> SA (A dead) ----
        {
            uint32_t ym[2][2][4][2];
#pragma unroll
            for (int hf = 0; hf < 2; ++hf)
#pragma unroll
                for (int mt = 0; mt < 2; ++mt)
#pragma unroll
                    for (int n = 0; n < 4; ++n) {
                        int col = n0w + n * 8 + q * 2;
                        int rA = m0 + hf * 32 + mt * 16 + g;
                        ym[hf][mt][n][0] = *(const uint32_t*)(g_Y1 + (size_t)sSrc[rA] * 128 + col);
                        ym[hf][mt][n][1] = *(const uint32_t*)(g_Y1 + (size_t)sSrc[rA + 8] * 128 + col);
                    }
            float acc[2][2][4][4];
            mma_stage2<8, 4>(sbase + SX_OFF, STRIDE128, sbase + WBUF_OFF, STRIDE128, m0, n0w, lane, acc);
            __syncthreads();   // [6] We2/x2 reads done
            cp_w(sbase + WBUF_OFF, IWC, 18432, tid);    // Wc (overlaps epilogue)
            if (tid == 0) sTile[0] = atomicAdd(&g_ticket, 1);   // next tile ticket
#pragma unroll
            for (int hf = 0; hf < 2; ++hf)
#pragma unroll
                for (int mt = 0; mt < 2; ++mt)
#pragma unroll
                    for (int n = 0; n < 4; ++n) {
                        int col = n0w + n * 8 + q * 2;
                        int rA = m0 + hf * 32 + mt * 16 + g;
                        __nv_bfloat162 hA = *(__nv_bfloat162*)&ym[hf][mt][n][0];
                        __nv_bfloat162 hB = *(__nv_bfloat162*)&ym[hf][mt][n][1];
                        *(uint32_t*)(smem + SA_OFF + rA * STRIDE128 + col * 2) =
                            pack2_bf16(acc[hf][mt][n][0] * __bfloat162float(hA.x),
                                       acc[hf][mt][n][1] * __bfloat162float(hA.y));
                        *(uint32_t*)(smem + SA_OFF + (rA + 8) * STRIDE128 + col * 2) =
                            pack2_bf16(acc[hf][mt][n][2] * __bfloat162float(hB.x),
                                       acc[hf][mt][n][3] * __bfloat162float(hB.y));
                    }
        }
        CP_WAIT0();
        __syncthreads();   // [7] p + Wc ready

        // ---- stage C (4Mx2N): m = tanh(p @ Wc); reduce-add to out[dst] ----
        {
            // preload destinations into registers so no smem reads remain after [8]
            int dReg[2], egReg[2];
#pragma unroll
            for (int mt = 0; mt < 2; ++mt) {
                int rA = m0c + mt * 16 + g;
                dReg[mt] = sDst[rA];          // row rA
                egReg[mt] = e0 + rA;
            }
            int dRegB[2], egRegB[2];
#pragma unroll
            for (int mt = 0; mt < 2; ++mt) {
                int rB = m0c + mt * 16 + g + 8;
                dRegB[mt] = sDst[rB];
                egRegB[mt] = e0 + rB;
            }

            float a6[2][4][4];
            mma_stage<8, 4>(sbase + SA_OFF, STRIDE128, sbase + WBUF_OFF, STRIDE64, m0c, n0c, lane, a6);
            __syncthreads();   // [8] stage C MMA done: SA/WBUF/sSrc/sDst free
            cp_w(sbase + WBUF_OFF, IWCB, 34816, tid);   // NEXT tile's Wcomb (hidden under epilogue+gather)

#pragma unroll
            for (int mt = 0; mt < 2; ++mt) {
#pragma unroll
                for (int n = 0; n < 4; ++n) {
                    int col = n0c + n * 8 + q * 2;
                    if (egReg[mt] < E) {
                        float* p = out + (size_t)dReg[mt] * 64 + col;
                        asm volatile("red.global.add.v2.f32 [%0], {%1,%2};"
                            :: "l"(p), "f"(fast_tanh(a6[mt][n][0])), "f"(fast_tanh(a6[mt][n][1])) : "memory");
                    }
                    if (egRegB[mt] < E) {
                        float* p = out + (size_t)dRegB[mt] * 64 + col;
                        asm volatile("red.global.add.v2.f32 [%0], {%1,%2};"
                            :: "l"(p), "f"(fast_tanh(a6[mt][n][2])), "f"(fast_tanh(a6[mt][n][3])) : "memory");
                    }
                }
            }
        }
        tile = sTile[0];   // written before [7], visible
    }
    CP_WAIT0();   // drain any in-flight weight stream before exit
}

extern "C" void kernel_launch(void* const* d_in, const int* in_sizes, int n_in,
                              void* d_out, int out_size) {
    const float* h   = (const float*)d_in[0];
    const float* eh  = (const float*)d_in[1];
    const float* Wn1 = (const float*)d_in[2];
    const float* bn1 = (const float*)d_in[3];
    const float* Wn2 = (const float*)d_in[4];
    const float* We1 = (const float*)d_in[5];
    const float* be1 = (const float*)d_in[6];
    const float* We2 = (const float*)d_in[7];
    const float* Wc  = (const float*)d_in[8];
    const float* Wue = (const float*)d_in[9];
    const int*   src = (const int*)d_in[10];
    const int*   dst = (const int*)d_in[11];
    float* out = (float*)d_out;

    int E = in_sizes[10];
    int Nn = in_sizes[0] / 64;
    if (Nn > N_MAX) Nn = N_MAX;
    int nTiles = (E + M_TILE - 1) / M_TILE;

    // reset dynamic tile ticket (graph-capturable)
    void* ticketAddr = nullptr;
    cudaGetSymbolAddress(&ticketAddr, g_ticket);
    cudaMemsetAsync(ticketAddr, 0, sizeof(int));

    int nNodeBlocks = (Nn + 127) / 128;
    cudaFuncSetAttribute(node_kernel, cudaFuncAttributeMaxDynamicSharedMemorySize, NSMEM_BYTES);
    node_kernel<<<nNodeBlocks + 160, NTHREADS, NSMEM_BYTES>>>(
        h, Wn1, bn1, Wn2, Wue, We1, We2, Wc, out, Nn, nNodeBlocks);

    int nSM = 148;
    cudaDeviceGetAttribute(&nSM, cudaDevAttrMultiProcessorCount, 0);
    int grid = 2 * nSM;
    if (grid > nTiles) grid = nTiles;

    cudaFuncSetAttribute(edge_kernel, cudaFuncAttributeMaxDynamicSharedMemorySize, ESMEM_BYTES);
    edge_kernel<<<grid, ETHREADS, ESMEM_BYTES>>>(h, eh, be1, src, dst, out, E, nTiles);
}